// round 1
// baseline (speedup 1.0000x reference)
#include <cuda_runtime.h>
#include <cstdint>

// Problem constants
#define BB 4
#define TT 32
#define NN 32
#define FF 16
#define GH 64
#define LSTM_IN 2048     // NN*GH
#define LSTM_H 4096
#define GATES 16384      // 4*LSTM_H
#define E_EDGES 256

// Scratch (device globals; no dynamic allocation allowed)
__device__ float g_A[NN * NN];
__device__ float g_seq[BB * TT * LSTM_IN];            // 1 MB
__device__ float g_xproj[TT * BB * GATES];            // 8 MB
__device__ float g_gates[BB * GATES];
__device__ float g_h[BB * LSTM_H];
__device__ float g_c[BB * LSTM_H];

// ---------- packed f32x2 helpers (sm_103a FFMA2 path) ----------
__device__ __forceinline__ unsigned long long pack2(float lo, float hi) {
    unsigned long long r;
    unsigned int l = __float_as_uint(lo), h = __float_as_uint(hi);
    asm("mov.b64 %0, {%1, %2};" : "=l"(r) : "r"(l), "r"(h));
    return r;
}
__device__ __forceinline__ void ffma2(unsigned long long& d,
                                      unsigned long long a,
                                      unsigned long long b) {
    asm("fma.rn.f32x2 %0, %1, %2, %0;" : "+l"(d) : "l"(a), "l"(b));
}
__device__ __forceinline__ float2 unpack2(unsigned long long v) {
    unsigned int l, h;
    asm("mov.b64 {%0, %1}, %2;" : "=r"(l), "=r"(h) : "l"(v));
    float2 r;
    r.x = __uint_as_float(l);
    r.y = __uint_as_float(h);
    return r;
}

// ---------- 1) adjacency build (handles int32 or int64 edge_index) ----------
__global__ void build_adj_kernel(const int* __restrict__ ei32) {
    __shared__ int is32flag;
    __shared__ int deg[NN];
    __shared__ float dinv[NN];
    __shared__ float As[NN * NN];
    int tid = threadIdx.x;
    if (tid == 0) is32flag = 0;
    for (int i = tid; i < NN; i += blockDim.x) deg[i] = 1;  // self loop
    for (int i = tid; i < NN * NN; i += blockDim.x) As[i] = 0.f;
    __syncthreads();
    // If stored as int64 (values < 32), every odd 32-bit word (high half) is 0.
    // 512 words is in-bounds for both dtypes.
    int any = 0;
    for (int w = tid * 2 + 1; w < 512; w += blockDim.x * 2) any |= ei32[w];
    if (any) atomicOr(&is32flag, 1);
    __syncthreads();
    const int is32 = is32flag;
    for (int e = tid; e < E_EDGES; e += blockDim.x) {
        int dst = is32 ? ei32[E_EDGES + e] : ei32[2 * (E_EDGES + e)];
        atomicAdd(&deg[dst], 1);
    }
    __syncthreads();
    for (int i = tid; i < NN; i += blockDim.x) dinv[i] = rsqrtf((float)deg[i]);
    __syncthreads();
    for (int e = tid; e < E_EDGES; e += blockDim.x) {
        int src = is32 ? ei32[e] : ei32[2 * e];
        int dst = is32 ? ei32[E_EDGES + e] : ei32[2 * (E_EDGES + e)];
        atomicAdd(&As[dst * NN + src], dinv[src] * dinv[dst]);
    }
    for (int n = tid; n < NN; n += blockDim.x)
        atomicAdd(&As[n * NN + n], dinv[n] * dinv[n]);
    __syncthreads();
    for (int i = tid; i < NN * NN; i += blockDim.x) g_A[i] = As[i];
}

// ---------- 2) LayerNorm + GCN x2 -> seq[bt][n*GH+g] ----------
__global__ void __launch_bounds__(256) gcn_kernel(
    const float* __restrict__ x, const float* __restrict__ ln_g,
    const float* __restrict__ ln_b, const float* __restrict__ W1,
    const float* __restrict__ b1, const float* __restrict__ W2,
    const float* __restrict__ b2) {
    __shared__ float xln[NN * FF];
    __shared__ float bufA[NN * GH];
    __shared__ float bufB[NN * GH];
    __shared__ float As[NN * NN];
    int tid = threadIdx.x;
    int bt = blockIdx.x;  // b*TT + t
    const float* xp = x + (size_t)bt * NN * FF;

    for (int i = tid; i < NN * NN; i += 256) As[i] = g_A[i];
    if (tid < NN) {
        float v[FF];
        float mu = 0.f;
#pragma unroll
        for (int f = 0; f < FF; f++) { v[f] = xp[tid * FF + f]; mu += v[f]; }
        mu *= (1.f / FF);
        float var = 0.f;
#pragma unroll
        for (int f = 0; f < FF; f++) { float d = v[f] - mu; var += d * d; }
        var *= (1.f / FF);
        float r = rsqrtf(var + 1e-5f);
#pragma unroll
        for (int f = 0; f < FF; f++)
            xln[tid * FF + f] = (v[f] - mu) * r * ln_g[f] + ln_b[f];
    }
    __syncthreads();
    // t1 = xln @ W1
    for (int o = tid; o < NN * GH; o += 256) {
        int n = o >> 6, g = o & 63;
        float s = 0.f;
#pragma unroll
        for (int f = 0; f < FF; f++) s += xln[n * FF + f] * W1[f * GH + g];
        bufA[o] = s;
    }
    __syncthreads();
    // agg1 = A @ t1 + b1
    for (int o = tid; o < NN * GH; o += 256) {
        int n = o >> 6, g = o & 63;
        float s = b1[g];
#pragma unroll 8
        for (int sn = 0; sn < NN; sn++) s += As[n * NN + sn] * bufA[sn * GH + g];
        bufB[o] = s;
    }
    __syncthreads();
    // t2 = agg1 @ W2
    for (int o = tid; o < NN * GH; o += 256) {
        int n = o >> 6, g = o & 63;
        float s = 0.f;
#pragma unroll 8
        for (int f = 0; f < GH; f++) s += bufB[n * GH + f] * W2[f * GH + g];
        bufA[o] = s;
    }
    __syncthreads();
    // out = A @ t2 + b2 -> seq
    for (int o = tid; o < NN * GH; o += 256) {
        int n = o >> 6, g = o & 63;
        float s = b2[g];
#pragma unroll 8
        for (int sn = 0; sn < NN; sn++) s += As[n * NN + sn] * bufA[sn * GH + g];
        g_seq[(size_t)bt * LSTM_IN + o] = s;
    }
}

// ---------- 3) x_proj = seq @ W_ih^T + (b_ih + b_hh) ----------
// M=128 (bt), N=16384 (gates), K=2048. Tile 128x128 per block, grid 128.
// Packed fp32x2 FFMA2 along the gate dimension.
__global__ void __launch_bounds__(256) xproj_gemm_kernel(
    const float* __restrict__ Wih, const float* __restrict__ b_ih,
    const float* __restrict__ b_hh) {
    __shared__ float Ss[16][128];
    __shared__ float Ws[16][128];
    int tid = threadIdx.x;
    int tx = tid & 15, ty = tid >> 4;
    int gbase = blockIdx.x * 128;
    unsigned long long acc[8][4];
#pragma unroll
    for (int i = 0; i < 8; i++)
#pragma unroll
        for (int p = 0; p < 4; p++) acc[i][p] = 0ull;

    for (int kc = 0; kc < 2048; kc += 16) {
#pragma unroll
        for (int i = 0; i < 2; i++) {
            int idx = tid + i * 256;  // 512 float4 tiles
            int row = idx >> 2, c = idx & 3;
            float4 v = *(const float4*)&g_seq[(size_t)row * 2048 + kc + c * 4];
            Ss[c * 4 + 0][row] = v.x;
            Ss[c * 4 + 1][row] = v.y;
            Ss[c * 4 + 2][row] = v.z;
            Ss[c * 4 + 3][row] = v.w;
            float4 w = *(const float4*)(Wih + (size_t)(gbase + row) * 2048 + kc + c * 4);
            Ws[c * 4 + 0][row] = w.x;
            Ws[c * 4 + 1][row] = w.y;
            Ws[c * 4 + 2][row] = w.z;
            Ws[c * 4 + 3][row] = w.w;
        }
        __syncthreads();
#pragma unroll
        for (int kk = 0; kk < 16; kk++) {
            float4 a0 = *(float4*)&Ss[kk][ty * 8];
            float4 a1 = *(float4*)&Ss[kk][ty * 8 + 4];
            float4 b0 = *(float4*)&Ws[kk][tx * 8];
            float4 b1 = *(float4*)&Ws[kk][tx * 8 + 4];
            unsigned long long bp[4] = {pack2(b0.x, b0.y), pack2(b0.z, b0.w),
                                        pack2(b1.x, b1.y), pack2(b1.z, b1.w)};
            float av[8] = {a0.x, a0.y, a0.z, a0.w, a1.x, a1.y, a1.z, a1.w};
#pragma unroll
            for (int i = 0; i < 8; i++) {
                unsigned long long ap = pack2(av[i], av[i]);
                ffma2(acc[i][0], ap, bp[0]);
                ffma2(acc[i][1], ap, bp[1]);
                ffma2(acc[i][2], ap, bp[2]);
                ffma2(acc[i][3], ap, bp[3]);
            }
        }
        __syncthreads();
    }
#pragma unroll
    for (int i = 0; i < 8; i++) {
        int m = ty * 8 + i;
        int t = m & 31, b = m >> 5;
        float* outp = g_xproj + (size_t)t * BB * GATES + (size_t)b * GATES + gbase + tx * 8;
#pragma unroll
        for (int p = 0; p < 4; p++) {
            float2 v = unpack2(acc[i][p]);
            int g = gbase + tx * 8 + 2 * p;
            outp[2 * p] = v.x + b_ih[g] + b_hh[g];
            outp[2 * p + 1] = v.y + b_ih[g + 1] + b_hh[g + 1];
        }
    }
}

// ---------- 4) init h,c ----------
__global__ void init_hc_kernel() {
    int idx = blockIdx.x * 256 + threadIdx.x;
    if (idx < BB * LSTM_H) { g_h[idx] = 0.f; g_c[idx] = 0.f; }
}

// ---------- 5) per-step gates = h @ W_hh^T + x_proj[t] ----------
// Warp per gate row g; lanes stride K in float4. DRAM-bound on W_hh.
__global__ void __launch_bounds__(256) gates_gemm_kernel(
    const float* __restrict__ Whh, int t) {
    int g = blockIdx.x * 8 + (threadIdx.x >> 5);
    int lane = threadIdx.x & 31;
    const float4* Wr = (const float4*)(Whh + (size_t)g * LSTM_H);
    const float4* h0 = (const float4*)(g_h);
    const float4* h1 = h0 + 1024;
    const float4* h2 = h0 + 2048;
    const float4* h3 = h0 + 3072;
    float a0 = 0.f, a1 = 0.f, a2 = 0.f, a3 = 0.f;
#pragma unroll 4
    for (int i = lane; i < 1024; i += 32) {
        float4 w = Wr[i];
        float4 x0 = h0[i], x1 = h1[i], x2 = h2[i], x3 = h3[i];
        a0 += w.x * x0.x + w.y * x0.y + w.z * x0.z + w.w * x0.w;
        a1 += w.x * x1.x + w.y * x1.y + w.z * x1.z + w.w * x1.w;
        a2 += w.x * x2.x + w.y * x2.y + w.z * x2.z + w.w * x2.w;
        a3 += w.x * x3.x + w.y * x3.y + w.z * x3.z + w.w * x3.w;
    }
#pragma unroll
    for (int off = 16; off; off >>= 1) {
        a0 += __shfl_xor_sync(0xffffffffu, a0, off);
        a1 += __shfl_xor_sync(0xffffffffu, a1, off);
        a2 += __shfl_xor_sync(0xffffffffu, a2, off);
        a3 += __shfl_xor_sync(0xffffffffu, a3, off);
    }
    if (lane == 0) {
        const float* xp = g_xproj + (size_t)t * BB * GATES + g;
        g_gates[0 * GATES + g] = a0 + xp[0 * GATES];
        g_gates[1 * GATES + g] = a1 + xp[1 * GATES];
        g_gates[2 * GATES + g] = a2 + xp[2 * GATES];
        g_gates[3 * GATES + g] = a3 + xp[3 * GATES];
    }
}

// ---------- 6) elementwise LSTM cell update ----------
__global__ void lstm_update_kernel() {
    int idx = blockIdx.x * 256 + threadIdx.x;  // < 16384
    int b = idx >> 12, j = idx & 4095;
    const float* gb = g_gates + (size_t)b * GATES;
    float gi = gb[j];
    float gf = gb[4096 + j];
    float gg = gb[8192 + j];
    float go = gb[12288 + j];
    float c = g_c[idx];
    float si = 1.f / (1.f + expf(-gi));
    float sf = 1.f / (1.f + expf(-gf));
    float so = 1.f / (1.f + expf(-go));
    c = sf * c + si * tanhf(gg);
    g_c[idx] = c;
    g_h[idx] = so * tanhf(c);
}

// ---------- 7) final FC: out[b,n] = h[b, n*128:(n+1)*128] . fc_W + fc_b ----------
__global__ void final_fc_kernel(const float* __restrict__ fcW,
                                const float* __restrict__ fcb,
                                float* __restrict__ out) {
    int tid = threadIdx.x;  // 128
    int b = tid >> 5, n = tid & 31;
    const float* hp = g_h + (size_t)b * LSTM_H + n * 128;
    float s = fcb[0];
#pragma unroll 8
    for (int l = 0; l < 128; l++) s += hp[l] * fcW[l];
    out[tid] = s;
}

extern "C" void kernel_launch(void* const* d_in, const int* in_sizes, int n_in,
                              void* d_out, int out_size) {
    const float* x    = (const float*)d_in[0];
    const int*   ei   = (const int*)d_in[1];
    const float* ln_g = (const float*)d_in[2];
    const float* ln_b = (const float*)d_in[3];
    const float* W1   = (const float*)d_in[4];
    const float* b1   = (const float*)d_in[5];
    const float* W2   = (const float*)d_in[6];
    const float* b2   = (const float*)d_in[7];
    const float* W_ih = (const float*)d_in[8];
    const float* b_ih = (const float*)d_in[9];
    const float* W_hh = (const float*)d_in[10];
    const float* b_hh = (const float*)d_in[11];
    const float* fc_W = (const float*)d_in[12];
    const float* fc_b = (const float*)d_in[13];
    float* out = (float*)d_out;

    build_adj_kernel<<<1, 256>>>(ei);
    gcn_kernel<<<128, 256>>>(x, ln_g, ln_b, W1, b1, W2, b2);
    xproj_gemm_kernel<<<128, 256>>>(W_ih, b_ih, b_hh);
    init_hc_kernel<<<64, 256>>>();
    for (int t = 0; t < TT; t++) {
        gates_gemm_kernel<<<2048, 256>>>(W_hh, t);
        lstm_update_kernel<<<64, 256>>>();
    }
    final_fc_kernel<<<1, 128>>>(fc_W, fc_b, out);
}